// round 16
// baseline (speedup 1.0000x reference)
#include <cuda_runtime.h>
#include <cstdint>

#define N_NODES 40000
#define N_EDGES 400000
#define H2f 0.01f
#define LN_EPS 1e-5f
#define KC 16

// ---------------- device scratch (allocation-free rule: __device__ globals) ----
__device__ float g_xn[N_NODES * 64];
__device__ float g_xn_old[N_NODES * 64];
__device__ float g_tmp_n[N_NODES * 64];
__device__ float g_si[N_NODES * 64];
__device__ float g_sj[N_NODES * 64];
__device__ float g_xe[N_EDGES * 64];
__device__ float g_xe_old[N_EDGES * 64];
__device__ float g_tmp_e[N_EDGES * 64];
__device__ double g_stats[16];   // zero-init; k_zero_stats restores at graph end

typedef unsigned long long u64;
// Pair-packed weights: wp[k*32 + o] = (W[2o][k], W[2o+1][k]).
__device__ u64 g_wpack[37888];

#define OFF_K1N 0
#define OFF_K2N 512
#define OFF_K1E 2560
#define OFF_K2E 3072
#define OFF_KE1 5120    /* stride 6144 per layer */
#define OFF_KE2 17408   /* stride 2048 */
#define OFF_KN1 21504   /* stride 6144 */
#define OFF_KN2 33792   /* stride 2048 */

#define B_XN 0
#define B_XN_OLD 1
#define B_TMP_N 2
#define B_SI 3
#define B_SJ 4
#define B_XE 5
#define B_XE_OLD 6
#define B_TMP_E 7
__device__ float* const g_tab[8] = {g_xn, g_xn_old, g_tmp_n, g_si,
                                    g_sj, g_xe, g_xe_old, g_tmp_e};

// ---------------- packed f32x2 helpers -----------------------------------------
__device__ __forceinline__ u64 pack2(float f) {
    u64 r;
    asm("mov.b64 %0, {%1, %1};" : "=l"(r) : "f"(f));
    return r;
}
__device__ __forceinline__ void fma2(u64& d, u64 a, u64 b) {
    asm("fma.rn.f32x2 %0, %1, %2, %0;" : "+l"(d) : "l"(a), "l"(b));
}
__device__ __forceinline__ float2 unpack2(u64 v) {
    float2 r;
    asm("mov.b64 {%0, %1}, %2;" : "=f"(r.x), "=f"(r.y) : "l"(v));
    return r;
}
__device__ __forceinline__ float4 ave4(float4 a, float4 b) {
    return make_float4((a.x + b.x) * 0.5f, (a.y + b.y) * 0.5f, (a.z + b.z) * 0.5f,
                       (a.w + b.w) * 0.5f);
}
__device__ __forceinline__ float4 sub4(float4 a, float4 b) {
    return make_float4(a.x - b.x, a.y - b.y, a.z - b.z, a.w - b.w);
}
__device__ __forceinline__ void redadd4(float* p, float4 v) {
    asm volatile("red.global.add.v4.f32 [%0], {%1,%2,%3,%4};" ::"l"(p), "f"(v.x),
                 "f"(v.y), "f"(v.z), "f"(v.w)
                 : "memory");
}
// Inline LN finalize in FLOAT math (FP64 divides were a 900us regression).
__device__ __forceinline__ float2 load_mr(int slot, float rcnt) {
    float s = (float)g_stats[slot * 2 + 0];
    float q = (float)g_stats[slot * 2 + 1];
    float m = s * rcnt;
    float var = fmaf(q, rcnt, -m * m);
    return make_float2(m, rsqrtf(var + LN_EPS));
}

// ---------------- block-level stat reduction -> double atomics ------------------
__device__ __forceinline__ void block_stats(float s, float q, int slot, float* scr) {
#pragma unroll
    for (int o = 16; o > 0; o >>= 1) {
        s += __shfl_down_sync(0xFFFFFFFFu, s, o);
        q += __shfl_down_sync(0xFFFFFFFFu, q, o);
    }
    int wid = threadIdx.x >> 5, lid = threadIdx.x & 31;
    int nw = (blockDim.x + 31) >> 5;
    __syncthreads();  // smem tiles no longer needed; safe to reuse
    if (lid == 0) { scr[wid] = s; scr[16 + wid] = q; }
    __syncthreads();
    if (threadIdx.x == 0) {
        float S = 0.f, Q = 0.f;
        for (int w = 0; w < nw; w++) { S += scr[w]; Q += scr[16 + w]; }
        atomicAdd(&g_stats[slot * 2 + 0], (double)S);
        atomicAdd(&g_stats[slot * 2 + 1], (double)Q);
    }
}

// ---------------- weight packing -------------------------------------------------
__global__ void k_packall(const float* __restrict__ K1N, const float* __restrict__ K2N,
                          const float* __restrict__ K1E, const float* __restrict__ K2E,
                          const float* __restrict__ KE1, const float* __restrict__ KE2,
                          const float* __restrict__ KN1, const float* __restrict__ KN2) {
    int t = blockIdx.x * blockDim.x + threadIdx.x;
    if (t >= 37888) return;
    const int Ks[12] = {16, 64, 16, 64, 192, 192, 64, 64, 192, 192, 64, 64};
    const int offs[12] = {OFF_K1N, OFF_K2N, OFF_K1E, OFF_K2E,
                          OFF_KE1, OFF_KE1 + 6144, OFF_KE2, OFF_KE2 + 2048,
                          OFF_KN1, OFF_KN1 + 6144, OFF_KN2, OFF_KN2 + 2048};
    const float* Ws[12] = {K1N, K2N, K1E, K2E, KE1, KE1 + 192 * 64, KE2, KE2 + 64 * 64,
                           KN1, KN1 + 192 * 64, KN2, KN2 + 64 * 64};
    int s = 0;
#pragma unroll
    for (int q = 1; q < 12; q++)
        if (t >= offs[q]) s = q;
    int loc = t - offs[s];
    int K = Ks[s];
    int k = loc >> 5, o = loc & 31;
    const float* W = Ws[s];
    float w0 = W[(2 * o) * K + k];
    float w1 = W[(2 * o + 1) * K + k];
    u64 r;
    asm("mov.b64 %0, {%1, %2};" : "=l"(r) : "f"(w0), "f"(w1));
    g_wpack[t] = r;
}

// ---------------- unified tiled GEMM --------------------------------------------
// out[P][64] = A[P][K] @ W[K][64].
// A tile staged in smem as PRE-BROADCAST u64 pairs (v,v): inner loop has ZERO
// packing MOVs (A reads are 8-way broadcast -> conflict-free despite 8B width).
// MODE 0: A = xraw channel-major [K][P]
// MODE 1: A = relu((in[P][64]-m)*r), m/r computed inline (float) from stats[mrslot]
// MODE 2: A = [ (xn_i+xn_j)/2 | xe | xn_i-xn_j ]
// MODE 3: A = [ (si+sj)/2 | si-sj | xn ]
// EPI  0: store out (+out2), optional stats
// EPI  1: store out (+out2) + red-scatter result rows to si/sj via iInd/jInd
// EPI  2: node leapfrog in place: xn = 2*xn - xn_old + H2*acc (no stats)
template <int MODE, int MT, int EPI>
__global__ void __launch_bounds__(MT, MT == 128 ? 3 : 2)
k_gemm(const float* __restrict__ xraw, const int* __restrict__ iInd,
       const int* __restrict__ jInd, int inid, int outid, int out2id, int woff, int P,
       int K, int slot, int mrslot, float mrrcnt) {
    extern __shared__ char smem[];
    u64* Asu = reinterpret_cast<u64*>(smem);                    // [KC][MT] broadcast
    u64* Bsu = reinterpret_cast<u64*>(smem + KC * MT * 8);      // [KC][32]
    const int PB = (256 + MT - 1) / MT;  // B chunk = 256 ulonglong2
    int tid = threadIdx.x;
    int p0 = blockIdx.x * MT;
    int gp = p0 + tid;
    bool valid = gp < P;
    int gps = valid ? gp : 0;

    const float4 *r0 = nullptr, *r1 = nullptr, *r2 = nullptr;
    float lm = 0.f, lr = 0.f;
    if (MODE == 1) {
        float2 mr = load_mr(mrslot, mrrcnt);
        lm = mr.x;
        lr = mr.y;
        r0 = reinterpret_cast<const float4*>(g_tab[inid] + (size_t)gps * 64);
    } else if (MODE == 2) {
        int i = valid ? iInd[gp] : 0;
        int j = valid ? jInd[gp] : 0;
        r0 = reinterpret_cast<const float4*>(g_xn + (size_t)i * 64);
        r1 = reinterpret_cast<const float4*>(g_xn + (size_t)j * 64);
        r2 = reinterpret_cast<const float4*>(g_xe + (size_t)gps * 64);
    } else if (MODE == 3) {
        r0 = reinterpret_cast<const float4*>(g_si + (size_t)gps * 64);
        r1 = reinterpret_cast<const float4*>(g_sj + (size_t)gps * 64);
        r2 = reinterpret_cast<const float4*>(g_xn + (size_t)gps * 64);
    }

    int tx = tid & 7;   // output octet
    int ty = tid >> 3;  // position octet
    u64 acc[8][4];
#pragma unroll
    for (int mm = 0; mm < 8; mm++)
#pragma unroll
        for (int q = 0; q < 4; q++) acc[mm][q] = 0ull;

    const u64* Wp = g_wpack + woff;
    int nchunk = K >> 4;

    float pa[16];
    float4 pf[8];
    ulonglong2 pb[PB];

    auto prefetch = [&](int c0) {
#pragma unroll
        for (int j = 0; j < PB; j++) {
            int idx = j * MT + tid;
            if (idx < 256) {
                int k = idx >> 4, o2 = (idx & 15) << 1;
                pb[j] =
                    *reinterpret_cast<const ulonglong2*>(Wp + (size_t)(c0 + k) * 32 + o2);
            }
        }
        if (MODE == 0) {
#pragma unroll
            for (int k = 0; k < KC; k++)
                pa[k] = valid ? xraw[(size_t)(c0 + k) * P + gp] : 0.f;
        } else if (MODE == 1) {
#pragma unroll
            for (int q = 0; q < 4; q++) pf[q] = r0[(c0 >> 2) + q];
        } else {
            if (c0 < 64) {
#pragma unroll
                for (int q = 0; q < 4; q++) {
                    pf[q] = r0[(c0 >> 2) + q];
                    pf[4 + q] = r1[(c0 >> 2) + q];
                }
            } else if (c0 < 128) {
                int b = (c0 - 64) >> 2;
                if (MODE == 2) {
#pragma unroll
                    for (int q = 0; q < 4; q++) pf[q] = r2[b + q];
                } else {
#pragma unroll
                    for (int q = 0; q < 4; q++) {
                        pf[q] = r0[b + q];
                        pf[4 + q] = r1[b + q];
                    }
                }
            } else {
                int b = (c0 - 128) >> 2;
                if (MODE == 2) {
#pragma unroll
                    for (int q = 0; q < 4; q++) {
                        pf[q] = r0[b + q];
                        pf[4 + q] = r1[b + q];
                    }
                } else {
#pragma unroll
                    for (int q = 0; q < 4; q++) pf[q] = r2[b + q];
                }
            }
        }
    };

    auto store_stage = [&](int c0) {
#pragma unroll
        for (int j = 0; j < PB; j++) {
            int idx = j * MT + tid;
            if (idx < 256) {
                int k = idx >> 4, o2 = (idx & 15) << 1;
                *reinterpret_cast<ulonglong2*>(&Bsu[k * 32 + o2]) = pb[j];
            }
        }
        if (MODE == 0) {
#pragma unroll
            for (int k = 0; k < KC; k++) Asu[k * MT + tid] = pack2(pa[k]);
        } else if (MODE == 1) {
#pragma unroll
            for (int q = 0; q < 4; q++) {
                float4 v = pf[q];
                float t0 = (v.x - lm) * lr, t1 = (v.y - lm) * lr;
                float t2 = (v.z - lm) * lr, t3 = (v.w - lm) * lr;
                t0 = t0 > 0.f ? t0 : 0.f;
                t1 = t1 > 0.f ? t1 : 0.f;
                t2 = t2 > 0.f ? t2 : 0.f;
                t3 = t3 > 0.f ? t3 : 0.f;
                if (!valid) { t0 = t1 = t2 = t3 = 0.f; }
                Asu[(q * 4 + 0) * MT + tid] = pack2(t0);
                Asu[(q * 4 + 1) * MT + tid] = pack2(t1);
                Asu[(q * 4 + 2) * MT + tid] = pack2(t2);
                Asu[(q * 4 + 3) * MT + tid] = pack2(t3);
            }
        } else {
            bool two = (c0 < 64) || (MODE == 2 ? c0 >= 128 : (c0 >= 64 && c0 < 128));
            bool isave = (c0 < 64);
#pragma unroll
            for (int q = 0; q < 4; q++) {
                float4 w;
                if (two) {
                    w = isave ? ave4(pf[q], pf[4 + q]) : sub4(pf[q], pf[4 + q]);
                } else {
                    w = pf[q];
                }
                if (!valid) w = make_float4(0.f, 0.f, 0.f, 0.f);
                Asu[(q * 4 + 0) * MT + tid] = pack2(w.x);
                Asu[(q * 4 + 1) * MT + tid] = pack2(w.y);
                Asu[(q * 4 + 2) * MT + tid] = pack2(w.z);
                Asu[(q * 4 + 3) * MT + tid] = pack2(w.w);
            }
        }
    };

    prefetch(0);
    for (int cb = 0; cb < nchunk; cb++) {
        store_stage(cb * KC);
        __syncthreads();
        if (cb + 1 < nchunk) prefetch((cb + 1) * KC);
#pragma unroll
        for (int k = 0; k < KC; k++) {
            const ulonglong2* Ap =
                reinterpret_cast<const ulonglong2*>(Asu + k * MT + ty * 8);
            ulonglong2 aA = Ap[0], aB = Ap[1], aC = Ap[2], aD = Ap[3];  // broadcast
            ulonglong2 b0 = *reinterpret_cast<const ulonglong2*>(&Bsu[k * 32 + tx * 4]);
            ulonglong2 b1 =
                *reinterpret_cast<const ulonglong2*>(&Bsu[k * 32 + tx * 4 + 2]);
            u64 av[8] = {aA.x, aA.y, aB.x, aB.y, aC.x, aC.y, aD.x, aD.y};
#pragma unroll
            for (int mm = 0; mm < 8; mm++) {
                fma2(acc[mm][0], av[mm], b0.x);
                fma2(acc[mm][1], av[mm], b0.y);
                fma2(acc[mm][2], av[mm], b1.x);
                fma2(acc[mm][3], av[mm], b1.y);
            }
        }
        __syncthreads();
    }

    // ---- epilogues
    float lsum = 0.f, lsq = 0.f;
    if (EPI == 2) {
        // node leapfrog in place: xn = 2*xn - xn_old + H2 * acc
#pragma unroll
        for (int mm = 0; mm < 8; mm++) {
            int pp = p0 + ty * 8 + mm;
            if (pp < P) {
                float2 v0 = unpack2(acc[mm][0]), v1 = unpack2(acc[mm][1]);
                float2 v2 = unpack2(acc[mm][2]), v3 = unpack2(acc[mm][3]);
                float4* xp = reinterpret_cast<float4*>(g_xn + (size_t)pp * 64 + tx * 8);
                const float4* op =
                    reinterpret_cast<const float4*>(g_xn_old + (size_t)pp * 64 + tx * 8);
                float4 x0 = xp[0], x1 = xp[1], o0 = op[0], o1 = op[1];
                float4 w0 = make_float4(2.f * x0.x - o0.x + H2f * v0.x,
                                        2.f * x0.y - o0.y + H2f * v0.y,
                                        2.f * x0.z - o0.z + H2f * v1.x,
                                        2.f * x0.w - o0.w + H2f * v1.y);
                float4 w1 = make_float4(2.f * x1.x - o1.x + H2f * v2.x,
                                        2.f * x1.y - o1.y + H2f * v2.y,
                                        2.f * x1.z - o1.z + H2f * v3.x,
                                        2.f * x1.w - o1.w + H2f * v3.y);
                xp[0] = w0;
                xp[1] = w1;
            }
        }
    } else {
        float* outp = g_tab[outid];
        float* out2p = out2id >= 0 ? g_tab[out2id] : nullptr;
#pragma unroll
        for (int mm = 0; mm < 8; mm++) {
            int pp = p0 + ty * 8 + mm;
            if (pp < P) {
                float2 v0 = unpack2(acc[mm][0]), v1 = unpack2(acc[mm][1]);
                float2 v2 = unpack2(acc[mm][2]), v3 = unpack2(acc[mm][3]);
                float4 w0 = make_float4(v0.x, v0.y, v1.x, v1.y);
                float4 w1 = make_float4(v2.x, v2.y, v3.x, v3.y);
                float4* dst = reinterpret_cast<float4*>(outp + (size_t)pp * 64 + tx * 8);
                dst[0] = w0;
                dst[1] = w1;
                if (out2p) {
                    float4* d2 =
                        reinterpret_cast<float4*>(out2p + (size_t)pp * 64 + tx * 8);
                    d2[0] = w0;
                    d2[1] = w1;
                }
                if (EPI == 1) {  // scatter result rows into si/sj
                    int i2 = __ldg(&iInd[pp]), j2 = __ldg(&jInd[pp]);
                    redadd4(g_si + (size_t)i2 * 64 + tx * 8, w0);
                    redadd4(g_si + (size_t)i2 * 64 + tx * 8 + 4, w1);
                    redadd4(g_sj + (size_t)j2 * 64 + tx * 8, w0);
                    redadd4(g_sj + (size_t)j2 * 64 + tx * 8 + 4, w1);
                }
                lsum += w0.x + w0.y + w0.z + w0.w + w1.x + w1.y + w1.z + w1.w;
                lsq += w0.x * w0.x + w0.y * w0.y + w0.z * w0.z + w0.w * w0.w +
                       w1.x * w1.x + w1.y * w1.y + w1.z * w1.z + w1.w * w1.w;
            }
        }
    }
    if (EPI != 2 && slot >= 0)
        block_stats(lsum, lsq, slot, reinterpret_cast<float*>(Asu));
}

// ---------------- small kernels --------------------------------------------------
__global__ void k_zero2(unsigned int n4) {
    unsigned int t = blockIdx.x * blockDim.x + threadIdx.x;
    float4 z = make_float4(0.f, 0.f, 0.f, 0.f);
    if (t < n4) {
        reinterpret_cast<float4*>(g_tab[B_SI])[t] = z;
        reinterpret_cast<float4*>(g_tab[B_SJ])[t] = z;
    }
}

__global__ void k_zero_stats() {
    if (threadIdx.x < 16) g_stats[threadIdx.x] = 0.0;
}

// xe = 2*xe - xe_old + H2 * LN(dxe); optionally scatter new xe rows into si/sj.
template <bool SCATTER>
__global__ void k_update_edge(const int* __restrict__ iInd, const int* __restrict__ jInd,
                              int mrslot, float mrrcnt) {
    float* __restrict__ xe = g_tab[B_XE];
    const float* __restrict__ xe_old = g_tab[B_XE_OLD];
    const float* __restrict__ dxe = g_tab[B_TMP_E];
    unsigned int t = blockIdx.x * blockDim.x + threadIdx.x;
    if (t >= (unsigned int)N_EDGES * 16u) return;
    float2 mr = load_mr(mrslot, mrrcnt);
    float m = mr.x, r = mr.y;
    float4 x = reinterpret_cast<float4*>(xe)[t];
    float4 o = reinterpret_cast<const float4*>(xe_old)[t];
    float4 d = reinterpret_cast<const float4*>(dxe)[t];
    float4 w;
    w.x = 2.f * x.x - o.x + H2f * ((d.x - m) * r);
    w.y = 2.f * x.y - o.y + H2f * ((d.y - m) * r);
    w.z = 2.f * x.z - o.z + H2f * ((d.z - m) * r);
    w.w = 2.f * x.w - o.w + H2f * ((d.w - m) * r);
    reinterpret_cast<float4*>(xe)[t] = w;
    if (SCATTER) {
        int e = t >> 4, q = t & 15;
        int i = __ldg(&iInd[e]), j = __ldg(&jInd[e]);
        redadd4(g_si + (size_t)i * 64 + q * 4, w);
        redadd4(g_sj + (size_t)j * 64 + q * 4, w);
    }
}

__global__ void k_close(const float* __restrict__ K, float* __restrict__ out) {
    __shared__ float sKs[64 * 32];  // [c][32] transposed
    const float* __restrict__ xn = g_tab[B_XN];
    for (int t = threadIdx.x; t < 64 * 32; t += blockDim.x) {
        int c = t >> 5, o = t & 31;
        sKs[t] = K[o * 64 + c];
    }
    __syncthreads();
    int p = blockIdx.x * blockDim.x + threadIdx.x;
    if (p >= N_NODES) return;
    const float4* x4 = reinterpret_cast<const float4*>(xn + (size_t)p * 64);
    u64 acc[16];
#pragma unroll
    for (int q = 0; q < 16; q++) acc[q] = 0ull;
#pragma unroll 2
    for (int c4 = 0; c4 < 16; c4++) {
        float4 v = x4[c4];
        float vv[4] = {v.x, v.y, v.z, v.w};
#pragma unroll
        for (int k = 0; k < 4; k++) {
            int c = c4 * 4 + k;
            u64 f2 = pack2(vv[k]);
            const ulonglong2* row = reinterpret_cast<const ulonglong2*>(sKs + c * 32);
#pragma unroll
            for (int q = 0; q < 8; q++) {
                ulonglong2 kk = row[q];
                fma2(acc[2 * q + 0], f2, kk.x);
                fma2(acc[2 * q + 1], f2, kk.y);
            }
        }
    }
#pragma unroll
    for (int q = 0; q < 8; q++) {
        float2 v0 = unpack2(acc[2 * q]), v1 = unpack2(acc[2 * q + 1]);
        out[(size_t)(4 * q + 0) * N_NODES + p] = v0.x;
        out[(size_t)(4 * q + 1) * N_NODES + p] = v0.y;
        out[(size_t)(4 * q + 2) * N_NODES + p] = v1.x;
        out[(size_t)(4 * q + 3) * N_NODES + p] = v1.y;
    }
}

// Fused final edge update + transpose: out[c][e] = 2*xe - xe_old + H2*LN(dxe).
__global__ void k_xe_out(float* __restrict__ out, int mrslot, float mrrcnt) {
    __shared__ float tile[32][33];
    const float* __restrict__ xe = g_tab[B_XE];
    const float* __restrict__ xe_old = g_tab[B_XE_OLD];
    const float* __restrict__ dxe = g_tab[B_TMP_E];
    float2 mr = load_mr(mrslot, mrrcnt);
    float m = mr.x, r = mr.y;
    int e0 = blockIdx.x * 32;
    int c0 = blockIdx.y * 32;
    int tx = threadIdx.x, ty = threadIdx.y;
    size_t idx = (size_t)(e0 + ty) * 64 + c0 + tx;
    float x = xe[idx], o = xe_old[idx], d = dxe[idx];
    tile[ty][tx] = 2.f * x - o + H2f * ((d - m) * r);
    __syncthreads();
    out[(size_t)(c0 + ty) * N_EDGES + e0 + tx] = tile[tx][ty];
}

// ---------------- launch --------------------------------------------------------
extern "C" void kernel_launch(void* const* d_in, const int* in_sizes, int n_in,
                              void* d_out, int out_size) {
    const float* xn_in = (const float*)d_in[0];
    const float* xe_in = (const float*)d_in[1];
    const int* iInd = (const int*)d_in[2];
    const int* jInd = (const int*)d_in[3];
    const float* K1N = (const float*)d_in[4];
    const float* K2N = (const float*)d_in[5];
    const float* K1E = (const float*)d_in[6];
    const float* K2E = (const float*)d_in[7];
    const float* KNc = (const float*)d_in[8];
    const float* KE1 = (const float*)d_in[9];
    const float* KE2 = (const float*)d_in[10];
    const float* KN1 = (const float*)d_in[11];
    const float* KN2 = (const float*)d_in[12];
    float* out = (float*)d_out;

    const int T = 256;
    const int MTE = 192;                       // edge tile: 2 CTAs/SM
    const int gmN = (N_NODES + 127) / 128;     // 313 blocks of 128 threads
    const int gmE = (N_EDGES + MTE - 1) / MTE; // 2084 blocks of 192 threads
    const size_t shN = KC * 128 * 8 + KC * 32 * 8;  // 20480
    const size_t shE = KC * MTE * 8 + KC * 32 * 8;  // 28672
    const float RN = 1.0f / (64.0f * N_NODES), RE = 1.0f / (64.0f * N_EDGES);
    const unsigned int n4N = (unsigned int)N_NODES * 16u;

    k_packall<<<(37888 + T - 1) / T, T>>>(K1N, K2N, K1E, K2E, KE1, KE2, KN1, KN2);
    k_zero2<<<(n4N + T - 1) / T, T>>>(n4N);  // scatter targets for layer 0

    // stats slots: 0=open-n, 1=open-e, layer l: KE1=2+3l, KE2=3+3l, KN1=4+3l
    // ---- open nodes
    k_gemm<0, 128, 0><<<gmN, 128, shN>>>(xn_in, nullptr, nullptr, -1, B_TMP_N, -1,
                                         OFF_K1N, N_NODES, 16, 0, -1, 0.f);
    k_gemm<1, 128, 0><<<gmN, 128, shN>>>(nullptr, nullptr, nullptr, B_TMP_N, B_XN,
                                         B_XN_OLD, OFF_K2N, N_NODES, 64, -1, 0, RN);

    // ---- open edges (convB also scatters xe rows into si/sj for layer 0)
    k_gemm<0, 192, 0><<<gmE, 192, shE>>>(xe_in, nullptr, nullptr, -1, B_TMP_E, -1,
                                         OFF_K1E, N_EDGES, 16, 1, -1, 0.f);
    k_gemm<1, 192, 1><<<gmE, 192, shE>>>(nullptr, iInd, jInd, B_TMP_E, B_XE, B_XE_OLD,
                                         OFF_K2E, N_EDGES, 64, -1, 1, RE);

    for (int l = 0; l < 2; l++) {
        int sE1 = 2 + 3 * l, sE2 = 3 + 3 * l, sN1 = 4 + 3 * l;
        // edge path: gather+concat+KE1 -> LN -> relu+KE2 (+stats for outer LN)
        k_gemm<2, 192, 0><<<gmE, 192, shE>>>(nullptr, iInd, jInd, -1, B_TMP_E, -1,
                                             OFF_KE1 + l * 6144, N_EDGES, 192, sE1, -1,
                                             0.f);
        k_gemm<1, 192, 0><<<gmE, 192, shE>>>(nullptr, nullptr, nullptr, B_TMP_E,
                                             B_TMP_E, -1, OFF_KE2 + l * 2048, N_EDGES,
                                             64, sE2, sE1, RE);

        // node path: [aveE, divE, xn]+KN1 -> LN -> relu+KN2 with fused leapfrog
        k_gemm<3, 128, 0><<<gmN, 128, shN>>>(nullptr, nullptr, nullptr, -1, B_TMP_N, -1,
                                             OFF_KN1 + l * 6144, N_NODES, 192, sN1, -1,
                                             0.f);
        k_gemm<1, 128, 2><<<gmN, 128, shN>>>(nullptr, nullptr, nullptr, B_TMP_N, -1, -1,
                                             OFF_KN2 + l * 2048, N_NODES, 64, -1, sN1,
                                             RN);

        if (l == 0) {
            // zero scatter targets for layer 1, then edge leapfrog + fused scatter
            k_zero2<<<(n4N + T - 1) / T, T>>>(n4N);
            k_update_edge<true><<<(N_EDGES * 16) / T, T>>>(iInd, jInd, sE2, RE);
        } else {
            // final layer: edge leapfrog fused into output transpose
            dim3 tb(32, 32), tg(N_EDGES / 32, 2);
            k_xe_out<<<tg, tb>>>(out + (size_t)32 * N_NODES, sE2, RE);
        }
    }

    // xn -> KNclose (channel-major); restore stats zeros for next graph replay
    k_close<<<(N_NODES + T - 1) / T, T>>>(KNc, out);
    k_zero_stats<<<1, 32>>>();
}

// round 17
// speedup vs baseline: 1.1129x; 1.1129x over previous
#include <cuda_runtime.h>
#include <cstdint>

#define N_NODES 40000
#define N_EDGES 400000
#define H2f 0.01f
#define LN_EPS 1e-5f
#define KC 16

// ---------------- device scratch (allocation-free rule: __device__ globals) ----
__device__ float g_xn[N_NODES * 64];
__device__ float g_xn_old[N_NODES * 64];
__device__ float g_tmp_n[N_NODES * 64];
__device__ float g_si[N_NODES * 64];
__device__ float g_sj[N_NODES * 64];
__device__ float g_xe[N_EDGES * 64];
__device__ float g_xe_old[N_EDGES * 64];
__device__ float g_tmp_e[N_EDGES * 64];
__device__ double g_stats[16];   // zero-init; k_zero_stats restores at graph end

typedef unsigned long long u64;
// Pair-packed weights: wp[k*32 + o] = (W[2o][k], W[2o+1][k]).
__device__ u64 g_wpack[37888];

#define OFF_K1N 0
#define OFF_K2N 512
#define OFF_K1E 2560
#define OFF_K2E 3072
#define OFF_KE1 5120    /* stride 6144 per layer */
#define OFF_KE2 17408   /* stride 2048 */
#define OFF_KN1 21504   /* stride 6144 */
#define OFF_KN2 33792   /* stride 2048 */

#define B_XN 0
#define B_XN_OLD 1
#define B_TMP_N 2
#define B_SI 3
#define B_SJ 4
#define B_XE 5
#define B_XE_OLD 6
#define B_TMP_E 7
__device__ float* const g_tab[8] = {g_xn, g_xn_old, g_tmp_n, g_si,
                                    g_sj, g_xe, g_xe_old, g_tmp_e};

// ---------------- packed f32x2 helpers -----------------------------------------
__device__ __forceinline__ u64 pack2(float f) {
    u64 r;
    asm("mov.b64 %0, {%1, %1};" : "=l"(r) : "f"(f));
    return r;
}
__device__ __forceinline__ void fma2(u64& d, u64 a, u64 b) {
    asm("fma.rn.f32x2 %0, %1, %2, %0;" : "+l"(d) : "l"(a), "l"(b));
}
__device__ __forceinline__ float2 unpack2(u64 v) {
    float2 r;
    asm("mov.b64 {%0, %1}, %2;" : "=f"(r.x), "=f"(r.y) : "l"(v));
    return r;
}
__device__ __forceinline__ float4 ave4(float4 a, float4 b) {
    return make_float4((a.x + b.x) * 0.5f, (a.y + b.y) * 0.5f, (a.z + b.z) * 0.5f,
                       (a.w + b.w) * 0.5f);
}
__device__ __forceinline__ float4 sub4(float4 a, float4 b) {
    return make_float4(a.x - b.x, a.y - b.y, a.z - b.z, a.w - b.w);
}
__device__ __forceinline__ void redadd4(float* p, float4 v) {
    asm volatile("red.global.add.v4.f32 [%0], {%1,%2,%3,%4};" ::"l"(p), "f"(v.x),
                 "f"(v.y), "f"(v.z), "f"(v.w)
                 : "memory");
}
// Inline LN finalize in FLOAT math (FP64 divides were a 900us regression).
__device__ __forceinline__ float2 load_mr(int slot, float rcnt) {
    float s = (float)g_stats[slot * 2 + 0];
    float q = (float)g_stats[slot * 2 + 1];
    float m = s * rcnt;
    float var = fmaf(q, rcnt, -m * m);
    return make_float2(m, rsqrtf(var + LN_EPS));
}

// ---------------- block-level stat reduction -> double atomics ------------------
__device__ __forceinline__ void block_stats(float s, float q, int slot, float* scr) {
#pragma unroll
    for (int o = 16; o > 0; o >>= 1) {
        s += __shfl_down_sync(0xFFFFFFFFu, s, o);
        q += __shfl_down_sync(0xFFFFFFFFu, q, o);
    }
    int wid = threadIdx.x >> 5, lid = threadIdx.x & 31;
    int nw = (blockDim.x + 31) >> 5;
    __syncthreads();  // smem tiles no longer needed; safe to reuse
    if (lid == 0) { scr[wid] = s; scr[16 + wid] = q; }
    __syncthreads();
    if (threadIdx.x == 0) {
        float S = 0.f, Q = 0.f;
        for (int w = 0; w < nw; w++) { S += scr[w]; Q += scr[16 + w]; }
        atomicAdd(&g_stats[slot * 2 + 0], (double)S);
        atomicAdd(&g_stats[slot * 2 + 1], (double)Q);
    }
}

// ---------------- weight packing -------------------------------------------------
__global__ void k_packall(const float* __restrict__ K1N, const float* __restrict__ K2N,
                          const float* __restrict__ K1E, const float* __restrict__ K2E,
                          const float* __restrict__ KE1, const float* __restrict__ KE2,
                          const float* __restrict__ KN1, const float* __restrict__ KN2) {
    int t = blockIdx.x * blockDim.x + threadIdx.x;
    if (t >= 37888) return;
    const int Ks[12] = {16, 64, 16, 64, 192, 192, 64, 64, 192, 192, 64, 64};
    const int offs[12] = {OFF_K1N, OFF_K2N, OFF_K1E, OFF_K2E,
                          OFF_KE1, OFF_KE1 + 6144, OFF_KE2, OFF_KE2 + 2048,
                          OFF_KN1, OFF_KN1 + 6144, OFF_KN2, OFF_KN2 + 2048};
    const float* Ws[12] = {K1N, K2N, K1E, K2E, KE1, KE1 + 192 * 64, KE2, KE2 + 64 * 64,
                           KN1, KN1 + 192 * 64, KN2, KN2 + 64 * 64};
    int s = 0;
#pragma unroll
    for (int q = 1; q < 12; q++)
        if (t >= offs[q]) s = q;
    int loc = t - offs[s];
    int K = Ks[s];
    int k = loc >> 5, o = loc & 31;
    const float* W = Ws[s];
    float w0 = W[(2 * o) * K + k];
    float w1 = W[(2 * o + 1) * K + k];
    u64 r;
    asm("mov.b64 %0, {%1, %2};" : "=l"(r) : "f"(w0), "f"(w1));
    g_wpack[t] = r;
}

// ---------------- unified tiled GEMM (double-buffered, 1 barrier/chunk) ---------
// out[P][64] = A[P][K] @ W[K][64].
// MODE 0: A = xraw channel-major [K][P]
// MODE 1: A = relu((in[P][64]-m)*r), m/r computed inline (float) from stats[mrslot]
// MODE 2: A = [ (xn_i+xn_j)/2 | xe | xn_i-xn_j ]
// MODE 3: A = [ (si+sj)/2 | si-sj | xn ]
// EPI  0: store out (+out2), optional stats
// EPI  1: store out (+out2) + red-scatter result rows to si/sj via iInd/jInd
// EPI  2: node leapfrog in place: xn = 2*xn - xn_old + H2*acc (no stats)
// Loop: sync; [prefetch(c+1) || compute(buf c&1) || store(c+1 -> other buf)]; sync.
// The store target was last READ in chunk c-1, protected by the previous barrier.
template <int MODE, int MT, int EPI>
__global__ void __launch_bounds__(MT, MT == 128 ? 3 : 2)
k_gemm(const float* __restrict__ xraw, const int* __restrict__ iInd,
       const int* __restrict__ jInd, int inid, int outid, int out2id, int woff, int P,
       int K, int slot, int mrslot, float mrrcnt) {
    extern __shared__ char smem[];
    float* Asf = reinterpret_cast<float*>(smem);                    // [2][KC][MT]
    u64* Bsu = reinterpret_cast<u64*>(smem + 2 * KC * MT * 4);      // [2][KC][32]
    const int PB = (256 + MT - 1) / MT;  // B chunk = 256 ulonglong2
    int tid = threadIdx.x;
    int p0 = blockIdx.x * MT;
    int gp = p0 + tid;
    bool valid = gp < P;
    int gps = valid ? gp : 0;

    const float4 *r0 = nullptr, *r1 = nullptr, *r2 = nullptr;
    float lm = 0.f, lr = 0.f;
    if (MODE == 1) {
        float2 mr = load_mr(mrslot, mrrcnt);
        lm = mr.x;
        lr = mr.y;
        r0 = reinterpret_cast<const float4*>(g_tab[inid] + (size_t)gps * 64);
    } else if (MODE == 2) {
        int i = valid ? iInd[gp] : 0;
        int j = valid ? jInd[gp] : 0;
        r0 = reinterpret_cast<const float4*>(g_xn + (size_t)i * 64);
        r1 = reinterpret_cast<const float4*>(g_xn + (size_t)j * 64);
        r2 = reinterpret_cast<const float4*>(g_xe + (size_t)gps * 64);
    } else if (MODE == 3) {
        r0 = reinterpret_cast<const float4*>(g_si + (size_t)gps * 64);
        r1 = reinterpret_cast<const float4*>(g_sj + (size_t)gps * 64);
        r2 = reinterpret_cast<const float4*>(g_xn + (size_t)gps * 64);
    }

    int tx = tid & 7;   // output octet
    int ty = tid >> 3;  // position octet
    u64 acc[8][4];
#pragma unroll
    for (int mm = 0; mm < 8; mm++)
#pragma unroll
        for (int q = 0; q < 4; q++) acc[mm][q] = 0ull;

    const u64* Wp = g_wpack + woff;
    int nchunk = K >> 4;

    float pa[16];
    float4 pf[8];
    ulonglong2 pb[PB];

    auto prefetch = [&](int c0) {
#pragma unroll
        for (int j = 0; j < PB; j++) {
            int idx = j * MT + tid;
            if (idx < 256) {
                int k = idx >> 4, o2 = (idx & 15) << 1;
                pb[j] =
                    *reinterpret_cast<const ulonglong2*>(Wp + (size_t)(c0 + k) * 32 + o2);
            }
        }
        if (MODE == 0) {
#pragma unroll
            for (int k = 0; k < KC; k++)
                pa[k] = valid ? xraw[(size_t)(c0 + k) * P + gp] : 0.f;
        } else if (MODE == 1) {
#pragma unroll
            for (int q = 0; q < 4; q++) pf[q] = r0[(c0 >> 2) + q];
        } else {
            if (c0 < 64) {
#pragma unroll
                for (int q = 0; q < 4; q++) {
                    pf[q] = r0[(c0 >> 2) + q];
                    pf[4 + q] = r1[(c0 >> 2) + q];
                }
            } else if (c0 < 128) {
                int b = (c0 - 64) >> 2;
                if (MODE == 2) {
#pragma unroll
                    for (int q = 0; q < 4; q++) pf[q] = r2[b + q];
                } else {
#pragma unroll
                    for (int q = 0; q < 4; q++) {
                        pf[q] = r0[b + q];
                        pf[4 + q] = r1[b + q];
                    }
                }
            } else {
                int b = (c0 - 128) >> 2;
                if (MODE == 2) {
#pragma unroll
                    for (int q = 0; q < 4; q++) {
                        pf[q] = r0[b + q];
                        pf[4 + q] = r1[b + q];
                    }
                } else {
#pragma unroll
                    for (int q = 0; q < 4; q++) pf[q] = r2[b + q];
                }
            }
        }
    };

    auto store_stage = [&](int c0, int buf) {
        u64* Bb = Bsu + buf * KC * 32;
        float* Ab = Asf + buf * KC * MT;
#pragma unroll
        for (int j = 0; j < PB; j++) {
            int idx = j * MT + tid;
            if (idx < 256) {
                int k = idx >> 4, o2 = (idx & 15) << 1;
                *reinterpret_cast<ulonglong2*>(&Bb[k * 32 + o2]) = pb[j];
            }
        }
        if (MODE == 0) {
#pragma unroll
            for (int k = 0; k < KC; k++) Ab[k * MT + tid] = pa[k];
        } else if (MODE == 1) {
#pragma unroll
            for (int q = 0; q < 4; q++) {
                float4 v = pf[q];
                float t0 = (v.x - lm) * lr, t1 = (v.y - lm) * lr;
                float t2 = (v.z - lm) * lr, t3 = (v.w - lm) * lr;
                t0 = t0 > 0.f ? t0 : 0.f;
                t1 = t1 > 0.f ? t1 : 0.f;
                t2 = t2 > 0.f ? t2 : 0.f;
                t3 = t3 > 0.f ? t3 : 0.f;
                if (!valid) { t0 = t1 = t2 = t3 = 0.f; }
                Ab[(q * 4 + 0) * MT + tid] = t0;
                Ab[(q * 4 + 1) * MT + tid] = t1;
                Ab[(q * 4 + 2) * MT + tid] = t2;
                Ab[(q * 4 + 3) * MT + tid] = t3;
            }
        } else {
            bool two = (c0 < 64) || (MODE == 2 ? c0 >= 128 : (c0 >= 64 && c0 < 128));
            bool isave = (c0 < 64);
#pragma unroll
            for (int q = 0; q < 4; q++) {
                float4 w;
                if (two) {
                    w = isave ? ave4(pf[q], pf[4 + q]) : sub4(pf[q], pf[4 + q]);
                } else {
                    w = pf[q];
                }
                if (!valid) w = make_float4(0.f, 0.f, 0.f, 0.f);
                Ab[(q * 4 + 0) * MT + tid] = w.x;
                Ab[(q * 4 + 1) * MT + tid] = w.y;
                Ab[(q * 4 + 2) * MT + tid] = w.z;
                Ab[(q * 4 + 3) * MT + tid] = w.w;
            }
        }
    };

    prefetch(0);
    store_stage(0, 0);
    __syncthreads();
    for (int cb = 0; cb < nchunk; cb++) {
        bool more = (cb + 1 < nchunk);
        if (more) prefetch((cb + 1) * KC);
        const float* Ab = Asf + (cb & 1) * KC * MT;
        const u64* Bb = Bsu + (cb & 1) * KC * 32;
#pragma unroll
        for (int k = 0; k < KC; k++) {
            float4 a0 = *reinterpret_cast<const float4*>(Ab + k * MT + ty * 8);
            float4 a1 = *reinterpret_cast<const float4*>(Ab + k * MT + ty * 8 + 4);
            ulonglong2 b0 = *reinterpret_cast<const ulonglong2*>(&Bb[k * 32 + tx * 4]);
            ulonglong2 b1 =
                *reinterpret_cast<const ulonglong2*>(&Bb[k * 32 + tx * 4 + 2]);
            float av[8] = {a0.x, a0.y, a0.z, a0.w, a1.x, a1.y, a1.z, a1.w};
#pragma unroll
            for (int mm = 0; mm < 8; mm++) {
                u64 am = pack2(av[mm]);
                fma2(acc[mm][0], am, b0.x);
                fma2(acc[mm][1], am, b0.y);
                fma2(acc[mm][2], am, b1.x);
                fma2(acc[mm][3], am, b1.y);
            }
        }
        if (more) store_stage((cb + 1) * KC, (cb + 1) & 1);  // other buffer
        __syncthreads();  // ONE barrier per chunk
    }

    // ---- epilogues
    float lsum = 0.f, lsq = 0.f;
    if (EPI == 2) {
        // node leapfrog in place: xn = 2*xn - xn_old + H2 * acc
#pragma unroll
        for (int mm = 0; mm < 8; mm++) {
            int pp = p0 + ty * 8 + mm;
            if (pp < P) {
                float2 v0 = unpack2(acc[mm][0]), v1 = unpack2(acc[mm][1]);
                float2 v2 = unpack2(acc[mm][2]), v3 = unpack2(acc[mm][3]);
                float4* xp = reinterpret_cast<float4*>(g_xn + (size_t)pp * 64 + tx * 8);
                const float4* op =
                    reinterpret_cast<const float4*>(g_xn_old + (size_t)pp * 64 + tx * 8);
                float4 x0 = xp[0], x1 = xp[1], o0 = op[0], o1 = op[1];
                float4 w0 = make_float4(2.f * x0.x - o0.x + H2f * v0.x,
                                        2.f * x0.y - o0.y + H2f * v0.y,
                                        2.f * x0.z - o0.z + H2f * v1.x,
                                        2.f * x0.w - o0.w + H2f * v1.y);
                float4 w1 = make_float4(2.f * x1.x - o1.x + H2f * v2.x,
                                        2.f * x1.y - o1.y + H2f * v2.y,
                                        2.f * x1.z - o1.z + H2f * v3.x,
                                        2.f * x1.w - o1.w + H2f * v3.y);
                xp[0] = w0;
                xp[1] = w1;
            }
        }
    } else {
        float* outp = g_tab[outid];
        float* out2p = out2id >= 0 ? g_tab[out2id] : nullptr;
#pragma unroll
        for (int mm = 0; mm < 8; mm++) {
            int pp = p0 + ty * 8 + mm;
            if (pp < P) {
                float2 v0 = unpack2(acc[mm][0]), v1 = unpack2(acc[mm][1]);
                float2 v2 = unpack2(acc[mm][2]), v3 = unpack2(acc[mm][3]);
                float4 w0 = make_float4(v0.x, v0.y, v1.x, v1.y);
                float4 w1 = make_float4(v2.x, v2.y, v3.x, v3.y);
                float4* dst = reinterpret_cast<float4*>(outp + (size_t)pp * 64 + tx * 8);
                dst[0] = w0;
                dst[1] = w1;
                if (out2p) {
                    float4* d2 =
                        reinterpret_cast<float4*>(out2p + (size_t)pp * 64 + tx * 8);
                    d2[0] = w0;
                    d2[1] = w1;
                }
                if (EPI == 1) {  // scatter result rows into si/sj
                    int i2 = __ldg(&iInd[pp]), j2 = __ldg(&jInd[pp]);
                    redadd4(g_si + (size_t)i2 * 64 + tx * 8, w0);
                    redadd4(g_si + (size_t)i2 * 64 + tx * 8 + 4, w1);
                    redadd4(g_sj + (size_t)j2 * 64 + tx * 8, w0);
                    redadd4(g_sj + (size_t)j2 * 64 + tx * 8 + 4, w1);
                }
                lsum += w0.x + w0.y + w0.z + w0.w + w1.x + w1.y + w1.z + w1.w;
                lsq += w0.x * w0.x + w0.y * w0.y + w0.z * w0.z + w0.w * w0.w +
                       w1.x * w1.x + w1.y * w1.y + w1.z * w1.z + w1.w * w1.w;
            }
        }
    }
    if (EPI != 2 && slot >= 0) block_stats(lsum, lsq, slot, Asf);
}

// ---------------- small kernels --------------------------------------------------
__global__ void k_zero2(unsigned int n4) {
    unsigned int t = blockIdx.x * blockDim.x + threadIdx.x;
    float4 z = make_float4(0.f, 0.f, 0.f, 0.f);
    if (t < n4) {
        reinterpret_cast<float4*>(g_tab[B_SI])[t] = z;
        reinterpret_cast<float4*>(g_tab[B_SJ])[t] = z;
    }
}

__global__ void k_zero_stats() {
    if (threadIdx.x < 16) g_stats[threadIdx.x] = 0.0;
}

// xe = 2*xe - xe_old + H2 * LN(dxe); optionally scatter new xe rows into si/sj.
template <bool SCATTER>
__global__ void k_update_edge(const int* __restrict__ iInd, const int* __restrict__ jInd,
                              int mrslot, float mrrcnt) {
    float* __restrict__ xe = g_tab[B_XE];
    const float* __restrict__ xe_old = g_tab[B_XE_OLD];
    const float* __restrict__ dxe = g_tab[B_TMP_E];
    unsigned int t = blockIdx.x * blockDim.x + threadIdx.x;
    if (t >= (unsigned int)N_EDGES * 16u) return;
    float2 mr = load_mr(mrslot, mrrcnt);
    float m = mr.x, r = mr.y;
    float4 x = reinterpret_cast<float4*>(xe)[t];
    float4 o = reinterpret_cast<const float4*>(xe_old)[t];
    float4 d = reinterpret_cast<const float4*>(dxe)[t];
    float4 w;
    w.x = 2.f * x.x - o.x + H2f * ((d.x - m) * r);
    w.y = 2.f * x.y - o.y + H2f * ((d.y - m) * r);
    w.z = 2.f * x.z - o.z + H2f * ((d.z - m) * r);
    w.w = 2.f * x.w - o.w + H2f * ((d.w - m) * r);
    reinterpret_cast<float4*>(xe)[t] = w;
    if (SCATTER) {
        int e = t >> 4, q = t & 15;
        int i = __ldg(&iInd[e]), j = __ldg(&jInd[e]);
        redadd4(g_si + (size_t)i * 64 + q * 4, w);
        redadd4(g_sj + (size_t)j * 64 + q * 4, w);
    }
}

__global__ void k_close(const float* __restrict__ K, float* __restrict__ out) {
    __shared__ float sKs[64 * 32];  // [c][32] transposed
    const float* __restrict__ xn = g_tab[B_XN];
    for (int t = threadIdx.x; t < 64 * 32; t += blockDim.x) {
        int c = t >> 5, o = t & 31;
        sKs[t] = K[o * 64 + c];
    }
    __syncthreads();
    int p = blockIdx.x * blockDim.x + threadIdx.x;
    if (p >= N_NODES) return;
    const float4* x4 = reinterpret_cast<const float4*>(xn + (size_t)p * 64);
    u64 acc[16];
#pragma unroll
    for (int q = 0; q < 16; q++) acc[q] = 0ull;
#pragma unroll 2
    for (int c4 = 0; c4 < 16; c4++) {
        float4 v = x4[c4];
        float vv[4] = {v.x, v.y, v.z, v.w};
#pragma unroll
        for (int k = 0; k < 4; k++) {
            int c = c4 * 4 + k;
            u64 f2 = pack2(vv[k]);
            const ulonglong2* row = reinterpret_cast<const ulonglong2*>(sKs + c * 32);
#pragma unroll
            for (int q = 0; q < 8; q++) {
                ulonglong2 kk = row[q];
                fma2(acc[2 * q + 0], f2, kk.x);
                fma2(acc[2 * q + 1], f2, kk.y);
            }
        }
    }
#pragma unroll
    for (int q = 0; q < 8; q++) {
        float2 v0 = unpack2(acc[2 * q]), v1 = unpack2(acc[2 * q + 1]);
        out[(size_t)(4 * q + 0) * N_NODES + p] = v0.x;
        out[(size_t)(4 * q + 1) * N_NODES + p] = v0.y;
        out[(size_t)(4 * q + 2) * N_NODES + p] = v1.x;
        out[(size_t)(4 * q + 3) * N_NODES + p] = v1.y;
    }
}

// Fused final edge update + transpose: out[c][e] = 2*xe - xe_old + H2*LN(dxe).
__global__ void k_xe_out(float* __restrict__ out, int mrslot, float mrrcnt) {
    __shared__ float tile[32][33];
    const float* __restrict__ xe = g_tab[B_XE];
    const float* __restrict__ xe_old = g_tab[B_XE_OLD];
    const float* __restrict__ dxe = g_tab[B_TMP_E];
    float2 mr = load_mr(mrslot, mrrcnt);
    float m = mr.x, r = mr.y;
    int e0 = blockIdx.x * 32;
    int c0 = blockIdx.y * 32;
    int tx = threadIdx.x, ty = threadIdx.y;
    size_t idx = (size_t)(e0 + ty) * 64 + c0 + tx;
    float x = xe[idx], o = xe_old[idx], d = dxe[idx];
    tile[ty][tx] = 2.f * x - o + H2f * ((d - m) * r);
    __syncthreads();
    out[(size_t)(c0 + ty) * N_EDGES + e0 + tx] = tile[tx][ty];
}

// ---------------- launch --------------------------------------------------------
extern "C" void kernel_launch(void* const* d_in, const int* in_sizes, int n_in,
                              void* d_out, int out_size) {
    const float* xn_in = (const float*)d_in[0];
    const float* xe_in = (const float*)d_in[1];
    const int* iInd = (const int*)d_in[2];
    const int* jInd = (const int*)d_in[3];
    const float* K1N = (const float*)d_in[4];
    const float* K2N = (const float*)d_in[5];
    const float* K1E = (const float*)d_in[6];
    const float* K2E = (const float*)d_in[7];
    const float* KNc = (const float*)d_in[8];
    const float* KE1 = (const float*)d_in[9];
    const float* KE2 = (const float*)d_in[10];
    const float* KN1 = (const float*)d_in[11];
    const float* KN2 = (const float*)d_in[12];
    float* out = (float*)d_out;

    const int T = 256;
    const int MTE = 192;                       // edge tile: 2 CTAs/SM
    const int gmN = (N_NODES + 127) / 128;     // 313 blocks of 128 threads
    const int gmE = (N_EDGES + MTE - 1) / MTE; // 2084 blocks of 192 threads
    const size_t shN = 2 * (KC * 128 * 4 + KC * 32 * 8);  // 24576
    const size_t shE = 2 * (KC * MTE * 4 + KC * 32 * 8);  // 32768
    const float RN = 1.0f / (64.0f * N_NODES), RE = 1.0f / (64.0f * N_EDGES);
    const unsigned int n4N = (unsigned int)N_NODES * 16u;

    k_packall<<<(37888 + T - 1) / T, T>>>(K1N, K2N, K1E, K2E, KE1, KE2, KN1, KN2);
    k_zero2<<<(n4N + T - 1) / T, T>>>(n4N);  // scatter targets for layer 0

    // stats slots: 0=open-n, 1=open-e, layer l: KE1=2+3l, KE2=3+3l, KN1=4+3l
    // ---- open nodes
    k_gemm<0, 128, 0><<<gmN, 128, shN>>>(xn_in, nullptr, nullptr, -1, B_TMP_N, -1,
                                         OFF_K1N, N_NODES, 16, 0, -1, 0.f);
    k_gemm<1, 128, 0><<<gmN, 128, shN>>>(nullptr, nullptr, nullptr, B_TMP_N, B_XN,
                                         B_XN_OLD, OFF_K2N, N_NODES, 64, -1, 0, RN);

    // ---- open edges (convB also scatters xe rows into si/sj for layer 0)
    k_gemm<0, 192, 0><<<gmE, 192, shE>>>(xe_in, nullptr, nullptr, -1, B_TMP_E, -1,
                                         OFF_K1E, N_EDGES, 16, 1, -1, 0.f);
    k_gemm<1, 192, 1><<<gmE, 192, shE>>>(nullptr, iInd, jInd, B_TMP_E, B_XE, B_XE_OLD,
                                         OFF_K2E, N_EDGES, 64, -1, 1, RE);

    for (int l = 0; l < 2; l++) {
        int sE1 = 2 + 3 * l, sE2 = 3 + 3 * l, sN1 = 4 + 3 * l;
        // edge path: gather+concat+KE1 -> LN -> relu+KE2 (+stats for outer LN)
        k_gemm<2, 192, 0><<<gmE, 192, shE>>>(nullptr, iInd, jInd, -1, B_TMP_E, -1,
                                             OFF_KE1 + l * 6144, N_EDGES, 192, sE1, -1,
                                             0.f);
        k_gemm<1, 192, 0><<<gmE, 192, shE>>>(nullptr, nullptr, nullptr, B_TMP_E,
                                             B_TMP_E, -1, OFF_KE2 + l * 2048, N_EDGES,
                                             64, sE2, sE1, RE);

        // node path: [aveE, divE, xn]+KN1 -> LN -> relu+KN2 with fused leapfrog
        k_gemm<3, 128, 0><<<gmN, 128, shN>>>(nullptr, nullptr, nullptr, -1, B_TMP_N, -1,
                                             OFF_KN1 + l * 6144, N_NODES, 192, sN1, -1,
                                             0.f);
        k_gemm<1, 128, 2><<<gmN, 128, shN>>>(nullptr, nullptr, nullptr, B_TMP_N, -1, -1,
                                             OFF_KN2 + l * 2048, N_NODES, 64, -1, sN1,
                                             RN);

        if (l == 0) {
            // zero scatter targets for layer 1, then edge leapfrog + fused scatter
            k_zero2<<<(n4N + T - 1) / T, T>>>(n4N);
            k_update_edge<true><<<(N_EDGES * 16) / T, T>>>(iInd, jInd, sE2, RE);
        } else {
            // final layer: edge leapfrog fused into output transpose
            dim3 tb(32, 32), tg(N_EDGES / 32, 2);
            k_xe_out<<<tg, tb>>>(out + (size_t)32 * N_NODES, sE2, RE);
        }
    }

    // xn -> KNclose (channel-major); restore stats zeros for next graph replay
    k_close<<<(N_NODES + T - 1) / T, T>>>(KNc, out);
    k_zero_stats<<<1, 32>>>();
}